// round 16
// baseline (speedup 1.0000x reference)
#include <cuda_runtime.h>
#include <math.h>

#define Dm 1024
#define Hm 4096
#define Lm 12
#define Vm 50277
#define NB 148
#define NT 1024
#define NWG (NB * 32)            // 4736 warps
#define NTH (NB * NT)

// ---------------- global scratch (allocation-free) ----------------
__device__ float g_p1[6144];          // k/v/r half-row partials: [mat][row][half]
__device__ float g_po[4 * Dm];
__device__ float g_fk[Hm], g_fr[Dm];
__device__ float g_frp[768];          // frw half-row partials for rows 640..1023
__device__ float g_pf[8 * Dm];        // fv half-chunk partials

// ---------------- grid barrier (R5 atomic version — proven best) ----------------
__device__ unsigned g_cnt3[3];
__device__ unsigned g_gen;

__device__ __forceinline__ unsigned ld_acq(const unsigned* p) {
    unsigned v;
    asm volatile("ld.acquire.gpu.global.u32 %0, [%1];" : "=r"(v) : "l"(p) : "memory");
    return v;
}
__device__ __forceinline__ unsigned atom_add_rel(unsigned* p, unsigned a) {
    unsigned v;
    asm volatile("atom.release.gpu.global.add.u32 %0, [%1], %2;" : "=r"(v) : "l"(p), "r"(a) : "memory");
    return v;
}
__device__ __forceinline__ void st_rel(unsigned* p, unsigned v) {
    asm volatile("st.release.gpu.global.u32 [%0], %1;" :: "l"(p), "r"(v) : "memory");
}
__device__ __forceinline__ void st_rlx(unsigned* p, unsigned v) {
    asm volatile("st.relaxed.gpu.global.u32 [%0], %1;" :: "l"(p), "r"(v) : "memory");
}

__device__ __forceinline__ void gsync() {
    __syncthreads();
    if (threadIdx.x == 0) {
        unsigned g = ld_acq(&g_gen);
        unsigned old = atom_add_rel(&g_cnt3[g % 3u], 1u);
        if (old == (unsigned)(NB - 1)) {
            st_rlx(&g_cnt3[(g + 2u) % 3u], 0u);
            st_rel(&g_gen, g + 1u);
        } else {
            while (ld_acq(&g_gen) == g) { }
        }
    }
    __syncthreads();
}

// ---------------- fire-and-forget L2 prefetch ----------------
__device__ __forceinline__ void pf_l2(const void* p, size_t bytes) {
    const char* c = (const char*)p;
    size_t start = ((size_t)(blockIdx.x * NT + threadIdx.x)) << 7;
    size_t step  = ((size_t)NTH) << 7;
    for (size_t i = start; i < bytes; i += step)
        asm volatile("prefetch.global.L2 [%0];" :: "l"(c + i));
}

// ---------------- reductions ----------------
__device__ __forceinline__ float warp_sum(float v) {
#pragma unroll
    for (int o = 16; o; o >>= 1) v += __shfl_down_sync(0xffffffffu, v, o);
    return v;
}

// one-pass dual reduction: returns (sum a, sum b) over the block
__device__ __forceinline__ float2 block_sum2(float a, float b, float* sbuf) {
    int lane = threadIdx.x & 31, wid = threadIdx.x >> 5;
#pragma unroll
    for (int o = 16; o; o >>= 1) {
        a += __shfl_down_sync(0xffffffffu, a, o);
        b += __shfl_down_sync(0xffffffffu, b, o);
    }
    __syncthreads();
    if (lane == 0) { sbuf[wid] = a; sbuf[32 + wid] = b; }
    __syncthreads();
    if (wid == 0) {
        float t = sbuf[lane], u = sbuf[32 + lane];
#pragma unroll
        for (int o = 16; o; o >>= 1) {
            t += __shfl_down_sync(0xffffffffu, t, o);
            u += __shfl_down_sync(0xffffffffu, u, o);
        }
        if (lane == 0) { sbuf[0] = t; sbuf[32] = u; }
    }
    __syncthreads();
    return make_float2(sbuf[0], sbuf[32]);
}

// one-pass LN over the 1024-wide vector (thread i owns element i)
__device__ __forceinline__ float ln1024(float v, const float* __restrict__ w,
                                        const float* __restrict__ b, float* sbuf) {
    float2 s = block_sum2(v, v * v, sbuf);
    float mu = s.x * (1.0f / Dm);
    float var = s.y * (1.0f / Dm) - mu * mu;
    return (v - mu) * rsqrtf(var + 1e-5f) * w[threadIdx.x] + b[threadIdx.x];
}

// ---------------- dot helpers ----------------
__device__ __forceinline__ float fma4(float4 a, float4 c, float acc) {
    return fmaf(a.x, c.x, fmaf(a.y, c.y, fmaf(a.z, c.z, fmaf(a.w, c.w, acc))));
}
__device__ __forceinline__ float dot8(const float4* __restrict__ w, const float* xs, int lane) {
    const float4* x4 = (const float4*)xs;
    float acc = 0.f;
#pragma unroll
    for (int j = 0; j < 8; j++) acc = fma4(__ldcs(w + j * 32 + lane), x4[j * 32 + lane], acc);
    return warp_sum(acc);
}
__device__ __forceinline__ float dot4(const float4* __restrict__ w, const float* xs, int lane) {
    const float4* x4 = (const float4*)xs;
    float acc = 0.f;
#pragma unroll
    for (int j = 0; j < 4; j++) acc = fma4(__ldcs(w + j * 32 + lane), x4[j * 32 + lane], acc);
    return warp_sum(acc);
}
__device__ __forceinline__ float dot2(const float4* __restrict__ w, const float* xs, int lane) {
    const float4* x4 = (const float4*)xs;
    float acc = fma4(__ldcs(w + lane), x4[lane], 0.f);
    acc = fma4(__ldcs(w + 32 + lane), x4[32 + lane], acc);
    return warp_sum(acc);
}

// ---------------- the whole network in one persistent kernel ----------------
__global__ __launch_bounds__(NT, 1) void rwkv_all(
    const int* __restrict__ tok, const float* __restrict__ state,
    const float* __restrict__ emb,
    const float* __restrict__ ln0w, const float* __restrict__ ln0b,
    const float* __restrict__ ln1w, const float* __restrict__ ln1b,
    const float* __restrict__ tmk, const float* __restrict__ tmv,
    const float* __restrict__ tmr, const float* __restrict__ tf,
    const float* __restrict__ td,
    const float* __restrict__ kw, const float* __restrict__ vw,
    const float* __restrict__ rw, const float* __restrict__ ow,
    const float* __restrict__ ln2w, const float* __restrict__ ln2b,
    const float* __restrict__ fmk, const float* __restrict__ fmr,
    const float* __restrict__ fkw, const float* __restrict__ fvw,
    const float* __restrict__ frw,
    const float* __restrict__ lnoutw, const float* __restrict__ lnoutb,
    const float* __restrict__ headw,
    float* __restrict__ logits, float* __restrict__ ns)
{
    __shared__ float s_v0[Dm], s_v1[Dm], s_v2[Dm];
    __shared__ float s_fk[Hm];
    __shared__ float s_red[64];

    const int tid = threadIdx.x;
    const int wid = tid >> 5, lane = tid & 31;
    const int gw = blockIdx.x * 32 + wid;
    const bool b0 = (blockIdx.x == 0);

    const size_t DD = (size_t)Dm * Dm * sizeof(float);
    const size_t HD = (size_t)Hm * Dm * sizeof(float);

    // ---- warm L2 with layer-0 phase-1 weights ----
    pf_l2(kw, DD); pf_l2(vw, DD); pf_l2(rw, DD);

    // ---- embed + ln0 ----
    float x = ln1024(emb[(size_t)(*tok) * Dm + tid], ln0w, ln0b, s_red);

    for (int l = 0; l < Lm; l++) {
        const float* s = state + (size_t)l * 5 * Dm;
        float* nsl = ns + (size_t)l * 5 * Dm;
        const size_t dd = (size_t)l * Dm * Dm;
        const size_t hd = (size_t)l * Hm * Dm;

        // ======== phase 1: LN1 + token-mix; k/v/r half-row dots, balanced dual ========
        {
            float xx = ln1024(x, ln1w + l * Dm, ln1b + l * Dm, s_red);
            float ss = s[Dm + tid];
            float mk = tmk[l * Dm + tid], mv = tmv[l * Dm + tid], mr = tmr[l * Dm + tid];
            s_v0[tid] = xx * mk + ss * (1.0f - mk);
            s_v1[tid] = xx * mv + ss * (1.0f - mv);
            s_v2[tid] = xx * mr + ss * (1.0f - mr);
            if (b0) nsl[Dm + tid] = xx;
        }
        __syncthreads();
        {
            int t0 = gw;
            int t1 = gw + NWG;
            bool has1 = (t1 < 6144);
            int mat0 = t0 >> 11, rem0 = t0 & 2047, row0 = rem0 >> 1, h0 = rem0 & 1;
            const float* W0 = (mat0 == 0) ? (kw + dd) : (mat0 == 1) ? (vw + dd) : (rw + dd);
            const float4* wp0 = (const float4*)(W0 + (size_t)row0 * Dm + h0 * 512);
            const float* xs0 = ((mat0 == 0) ? s_v0 : (mat0 == 1) ? s_v1 : s_v2) + h0 * 512;
            int mat1 = t1 >> 11, rem1 = t1 & 2047, row1 = rem1 >> 1, h1 = rem1 & 1;
            const float* W1 = (mat1 == 0) ? (kw + dd) : (mat1 == 1) ? (vw + dd) : (rw + dd);
            const float4* wp1 = (const float4*)(W1 + (size_t)row1 * Dm + h1 * 512);
            const float* xs1 = ((mat1 == 0) ? s_v0 : (mat1 == 1) ? s_v1 : s_v2) + h1 * 512;

            float4 a0[4], a1[4];
#pragma unroll
            for (int j = 0; j < 4; j++) a0[j] = __ldcs(wp0 + j * 32 + lane);
            if (has1) {
#pragma unroll
                for (int j = 0; j < 4; j++) a1[j] = __ldcs(wp1 + j * 32 + lane);
            }
            const float4* x40 = (const float4*)xs0;
            float acc0 = 0.f;
#pragma unroll
            for (int j = 0; j < 4; j++) acc0 = fma4(a0[j], x40[j * 32 + lane], acc0);
            acc0 = warp_sum(acc0);
            if (lane == 0) __stcg(&g_p1[t0], acc0);
            if (has1) {
                const float4* x41 = (const float4*)xs1;
                float acc1 = 0.f;
#pragma unroll
                for (int j = 0; j < 4; j++) acc1 = fma4(a1[j], x41[j * 32 + lane], acc1);
                acc1 = warp_sum(acc1);
                if (lane == 0) __stcg(&g_p1[t1], acc1);
            }
        }
        pf_l2(ow + dd, DD);
        gsync();

        // ======== phase 2: WKV (combine partials) + ow quarter-row dots ========
        {
            float k = __ldcg(&g_p1[2 * tid])        + __ldcg(&g_p1[2 * tid + 1]);
            float v = __ldcg(&g_p1[2048 + 2 * tid]) + __ldcg(&g_p1[2048 + 2 * tid + 1]);
            float rp = __ldcg(&g_p1[4096 + 2 * tid]) + __ldcg(&g_p1[4096 + 2 * tid + 1]);
            float r = 1.0f / (1.0f + expf(-rp));
            float aa = s[2 * Dm + tid], bb = s[3 * Dm + tid], pp = s[4 * Dm + tid];
            float ww = tf[l * Dm + tid] + k;
            float p = fmaxf(pp, ww);
            float e1 = expf(pp - p), e2 = expf(ww - p);
            float wkv = (e1 * aa + e2 * v) / (e1 * bb + e2);
            float ww2 = pp + td[l * Dm + tid];
            float p2 = fmaxf(ww2, k);
            float f1 = expf(ww2 - p2), f2 = expf(k - p2);
            s_v0[tid] = r * wkv;
            if (b0) {
                nsl[2 * Dm + tid] = f1 * aa + f2 * v;
                nsl[3 * Dm + tid] = f1 * bb + f2;
                nsl[4 * Dm + tid] = p2;
            }
        }
        __syncthreads();
        for (int t = gw; t < 4 * Dm; t += NWG) {
            int row = t >> 2, ch = t & 3;
            float acc = dot2((const float4*)(ow + dd + (size_t)row * Dm + ch * 256),
                             s_v0 + ch * 256, lane);
            if (lane == 0) __stcg(&g_po[ch * Dm + row], acc);
        }
        pf_l2(fkw + hd, HD); pf_l2(frw + dd, DD);
        gsync();

        // ======== phase 3: residual + LN2 + FFN mix; fk/fr dots (half-row tail) ========
        x = x + __ldcg(&g_po[tid]) + __ldcg(&g_po[Dm + tid])
              + __ldcg(&g_po[2 * Dm + tid]) + __ldcg(&g_po[3 * Dm + tid]);
        {
            float yy = ln1024(x, ln2w + l * Dm, ln2b + l * Dm, s_red);
            float sf = s[tid];
            float mk = fmk[l * Dm + tid], mr = fmr[l * Dm + tid];
            s_v0[tid] = yy * mk + sf * (1.0f - mk);
            s_v1[tid] = yy * mr + sf * (1.0f - mr);
            if (b0) nsl[tid] = yy;
        }
        __syncthreads();
        {
            // first task: full row gw (fkw rows 0..4095, frw rows 0..639)
            bool isk = (gw < Hm);
            const float* W = isk ? (fkw + hd + (size_t)gw * Dm)
                                 : (frw + dd + (size_t)(gw - Hm) * Dm);
            float acc = dot8((const float4*)W, isk ? s_v0 : s_v1, lane);
            if (lane == 0) {
                if (isk) { float u = fmaxf(acc, 0.0f); __stcg(&g_fk[gw], u * u); }
                else     { __stcg(&g_fr[gw - Hm], 1.0f / (1.0f + expf(-acc))); }
            }
            // tail: frw rows 640..1023 as 768 half-row dot4s on warps 0..767
            if (gw < 768) {
                int frow = 640 + (gw >> 1), half = gw & 1;
                float a2 = dot4((const float4*)(frw + dd + (size_t)frow * Dm + half * 512),
                                s_v1 + half * 512, lane);
                if (lane == 0) __stcg(&g_frp[gw], a2);
            }
        }
        pf_l2(fvw + hd, HD);
        gsync();

        // ======== phase 4: fv half-chunk dots, balanced dual (8192 tasks) ========
        for (int j = tid; j < Hm; j += NT) s_fk[j] = __ldcg(&g_fk[j]);
        __syncthreads();
        {
            int t0 = gw, t1 = gw + NWG;
            bool has1 = (t1 < 8192);
            int row0 = t0 >> 3, ch0 = t0 & 7;
            int row1 = t1 >> 3, ch1 = t1 & 7;
            const float4* wp0 = (const float4*)(fvw + hd + (size_t)row0 * Hm + ch0 * 512);
            const float4* wp1 = (const float4*)(fvw + hd + (size_t)row1 * Hm + ch1 * 512);
            float4 a0[4], a1[4];
#pragma unroll
            for (int j = 0; j < 4; j++) a0[j] = __ldcs(wp0 + j * 32 + lane);
            if (has1) {
#pragma unroll
                for (int j = 0; j < 4; j++) a1[j] = __ldcs(wp1 + j * 32 + lane);
            }
            const float4* x40 = (const float4*)(s_fk + ch0 * 512);
            float acc0 = 0.f;
#pragma unroll
            for (int j = 0; j < 4; j++) acc0 = fma4(a0[j], x40[j * 32 + lane], acc0);
            acc0 = warp_sum(acc0);
            if (lane == 0) __stcg(&g_pf[ch0 * Dm + row0], acc0);
            if (has1) {
                const float4* x41 = (const float4*)(s_fk + ch1 * 512);
                float acc1 = 0.f;
#pragma unroll
                for (int j = 0; j < 4; j++) acc1 = fma4(a1[j], x41[j * 32 + lane], acc1);
                acc1 = warp_sum(acc1);
                if (lane == 0) __stcg(&g_pf[ch1 * Dm + row1], acc1);
            }
        }
        if (l + 1 < Lm) {
            const size_t dd2 = (size_t)(l + 1) * Dm * Dm;
            pf_l2(kw + dd2, DD); pf_l2(vw + dd2, DD); pf_l2(rw + dd2, DD);
        }
        if (l >= Lm - 4) {
            const size_t CH = (size_t)15 * 1024 * 1024;
            pf_l2((const char*)headw + (size_t)(l - (Lm - 4)) * CH, CH);
        }
        gsync();

        // ---- residual update for next layer ----
        {
            float pf = 0.f;
#pragma unroll
            for (int c = 0; c < 8; c++) pf += __ldcg(&g_pf[c * Dm + tid]);
            float fr;
            if (tid < 640) {
                fr = __ldcg(&g_fr[tid]);
            } else {
                int h = 2 * (tid - 640);
                fr = 1.0f / (1.0f + expf(-(__ldcg(&g_frp[h]) + __ldcg(&g_frp[h + 1]))));
            }
            x = x + fr * pf;
        }
    }

    // ---- final LN + head matvec (2 rows/warp in flight) ----
    {
        float xf = ln1024(x, lnoutw, lnoutb, s_red);
        s_v0[tid] = xf;
    }
    __syncthreads();
    for (int t = gw; t < Vm; t += 2 * NWG) {
        int t2 = t + NWG;
        const float4* w0 = (const float4*)(headw + (size_t)t * Dm);
        const float4* x4 = (const float4*)s_v0;
        float a0 = 0.f, a1 = 0.f;
        if (t2 < Vm) {
            const float4* w1 = (const float4*)(headw + (size_t)t2 * Dm);
#pragma unroll
            for (int j = 0; j < 8; j++) {
                float4 p = __ldcs(w0 + j * 32 + lane);
                float4 q = __ldcs(w1 + j * 32 + lane);
                float4 c = x4[j * 32 + lane];
                a0 = fma4(p, c, a0);
                a1 = fma4(q, c, a1);
            }
            a0 = warp_sum(a0); a1 = warp_sum(a1);
            if (lane == 0) { logits[t] = a0; logits[t2] = a1; }
        } else {
#pragma unroll
            for (int j = 0; j < 8; j++) a0 = fma4(__ldcs(w0 + j * 32 + lane), x4[j * 32 + lane], a0);
            a0 = warp_sum(a0);
            if (lane == 0) logits[t] = a0;
        }
    }
}

// ---------------- launch ----------------
extern "C" void kernel_launch(void* const* d_in, const int* in_sizes, int n_in,
                              void* d_out, int out_size) {
    const int*   tok    = (const int*)  d_in[0];
    const float* state  = (const float*)d_in[1];
    const float* emb    = (const float*)d_in[2];
    const float* ln0w   = (const float*)d_in[3];
    const float* ln0b   = (const float*)d_in[4];
    const float* ln1w   = (const float*)d_in[5];
    const float* ln1b   = (const float*)d_in[6];
    const float* tmk    = (const float*)d_in[7];
    const float* tmv    = (const float*)d_in[8];
    const float* tmr    = (const float*)d_in[9];
    const float* tf     = (const float*)d_in[10];
    const float* td     = (const float*)d_in[11];
    const float* kw     = (const float*)d_in[12];
    const float* vw     = (const float*)d_in[13];
    const float* rw     = (const float*)d_in[14];
    const float* ow     = (const float*)d_in[15];
    const float* ln2w   = (const float*)d_in[16];
    const float* ln2b   = (const float*)d_in[17];
    const float* fmk    = (const float*)d_in[18];
    const float* fmr    = (const float*)d_in[19];
    const float* fkw    = (const float*)d_in[20];
    const float* fvw    = (const float*)d_in[21];
    const float* frw    = (const float*)d_in[22];
    const float* lnoutw = (const float*)d_in[23];
    const float* lnoutb = (const float*)d_in[24];
    const float* headw  = (const float*)d_in[25];

    float* logits = (float*)d_out;
    float* ns     = (float*)d_out + Vm;

    rwkv_all<<<NB, NT>>>(tok, state, emb, ln0w, ln0b, ln1w, ln1b,
                         tmk, tmv, tmr, tf, td, kw, vw, rw, ow,
                         ln2w, ln2b, fmk, fmr, fkw, fvw, frw,
                         lnoutw, lnoutb, headw, logits, ns);
}

// round 17
// speedup vs baseline: 1.1054x; 1.1054x over previous
#include <cuda_runtime.h>
#include <math.h>

#define Dm 1024
#define Hm 4096
#define Lm 12
#define Vm 50277
#define NB 148
#define NT 1024
#define NWG (NB * 32)            // 4736 warps
#define NTH (NB * NT)

// ---------------- global scratch (allocation-free) ----------------
__device__ float g_p1[6144];          // k/v/r half-row partials: [mat][row][half]
__device__ float g_po[4 * Dm];
__device__ float g_fk[Hm], g_fr[Dm];
__device__ float g_pf[4 * Dm];

// ---------------- grid barrier (R5 atomic version — proven best) ----------------
__device__ unsigned g_cnt3[3];
__device__ unsigned g_gen;

__device__ __forceinline__ unsigned ld_acq(const unsigned* p) {
    unsigned v;
    asm volatile("ld.acquire.gpu.global.u32 %0, [%1];" : "=r"(v) : "l"(p) : "memory");
    return v;
}
__device__ __forceinline__ unsigned atom_add_rel(unsigned* p, unsigned a) {
    unsigned v;
    asm volatile("atom.release.gpu.global.add.u32 %0, [%1], %2;" : "=r"(v) : "l"(p), "r"(a) : "memory");
    return v;
}
__device__ __forceinline__ void st_rel(unsigned* p, unsigned v) {
    asm volatile("st.release.gpu.global.u32 [%0], %1;" :: "l"(p), "r"(v) : "memory");
}
__device__ __forceinline__ void st_rlx(unsigned* p, unsigned v) {
    asm volatile("st.relaxed.gpu.global.u32 [%0], %1;" :: "l"(p), "r"(v) : "memory");
}

__device__ __forceinline__ void gsync() {
    __syncthreads();
    if (threadIdx.x == 0) {
        unsigned g = ld_acq(&g_gen);
        unsigned old = atom_add_rel(&g_cnt3[g % 3u], 1u);
        if (old == (unsigned)(NB - 1)) {
            st_rlx(&g_cnt3[(g + 2u) % 3u], 0u);
            st_rel(&g_gen, g + 1u);
        } else {
            while (ld_acq(&g_gen) == g) { }
        }
    }
    __syncthreads();
}

// ---------------- fire-and-forget L2 prefetch ----------------
__device__ __forceinline__ void pf_l2(const void* p, size_t bytes) {
    const char* c = (const char*)p;
    size_t start = ((size_t)(blockIdx.x * NT + threadIdx.x)) << 7;
    size_t step  = ((size_t)NTH) << 7;
    for (size_t i = start; i < bytes; i += step)
        asm volatile("prefetch.global.L2 [%0];" :: "l"(c + i));
}

// ---------------- reductions ----------------
__device__ __forceinline__ float warp_sum(float v) {
#pragma unroll
    for (int o = 16; o; o >>= 1) v += __shfl_down_sync(0xffffffffu, v, o);
    return v;
}

// one-pass dual reduction: returns (sum a, sum b) over the block
__device__ __forceinline__ float2 block_sum2(float a, float b, float* sbuf) {
    int lane = threadIdx.x & 31, wid = threadIdx.x >> 5;
#pragma unroll
    for (int o = 16; o; o >>= 1) {
        a += __shfl_down_sync(0xffffffffu, a, o);
        b += __shfl_down_sync(0xffffffffu, b, o);
    }
    __syncthreads();
    if (lane == 0) { sbuf[wid] = a; sbuf[32 + wid] = b; }
    __syncthreads();
    if (wid == 0) {
        float t = sbuf[lane], u = sbuf[32 + lane];
#pragma unroll
        for (int o = 16; o; o >>= 1) {
            t += __shfl_down_sync(0xffffffffu, t, o);
            u += __shfl_down_sync(0xffffffffu, u, o);
        }
        if (lane == 0) { sbuf[0] = t; sbuf[32] = u; }
    }
    __syncthreads();
    return make_float2(sbuf[0], sbuf[32]);
}

// one-pass LN over the 1024-wide vector (thread i owns element i)
__device__ __forceinline__ float ln1024(float v, const float* __restrict__ w,
                                        const float* __restrict__ b, float* sbuf) {
    float2 s = block_sum2(v, v * v, sbuf);
    float mu = s.x * (1.0f / Dm);
    float var = s.y * (1.0f / Dm) - mu * mu;
    return (v - mu) * rsqrtf(var + 1e-5f) * w[threadIdx.x] + b[threadIdx.x];
}

// ---------------- dot helpers ----------------
__device__ __forceinline__ float fma4(float4 a, float4 c, float acc) {
    return fmaf(a.x, c.x, fmaf(a.y, c.y, fmaf(a.z, c.z, fmaf(a.w, c.w, acc))));
}
__device__ __forceinline__ float dot8(const float4* __restrict__ w, const float* xs, int lane) {
    const float4* x4 = (const float4*)xs;
    float acc = 0.f;
#pragma unroll
    for (int j = 0; j < 8; j++) acc = fma4(__ldcs(w + j * 32 + lane), x4[j * 32 + lane], acc);
    return warp_sum(acc);
}
__device__ __forceinline__ float dot2(const float4* __restrict__ w, const float* xs, int lane) {
    const float4* x4 = (const float4*)xs;
    float acc = fma4(__ldcs(w + lane), x4[lane], 0.f);
    acc = fma4(__ldcs(w + 32 + lane), x4[32 + lane], acc);
    return warp_sum(acc);
}

// ---------------- the whole network in one persistent kernel ----------------
__global__ __launch_bounds__(NT, 1) void rwkv_all(
    const int* __restrict__ tok, const float* __restrict__ state,
    const float* __restrict__ emb,
    const float* __restrict__ ln0w, const float* __restrict__ ln0b,
    const float* __restrict__ ln1w, const float* __restrict__ ln1b,
    const float* __restrict__ tmk, const float* __restrict__ tmv,
    const float* __restrict__ tmr, const float* __restrict__ tf,
    const float* __restrict__ td,
    const float* __restrict__ kw, const float* __restrict__ vw,
    const float* __restrict__ rw, const float* __restrict__ ow,
    const float* __restrict__ ln2w, const float* __restrict__ ln2b,
    const float* __restrict__ fmk, const float* __restrict__ fmr,
    const float* __restrict__ fkw, const float* __restrict__ fvw,
    const float* __restrict__ frw,
    const float* __restrict__ lnoutw, const float* __restrict__ lnoutb,
    const float* __restrict__ headw,
    float* __restrict__ logits, float* __restrict__ ns)
{
    __shared__ float s_v0[Dm], s_v1[Dm], s_v2[Dm];
    __shared__ float s_fk[Hm];
    __shared__ float s_red[64];

    const int tid = threadIdx.x;
    const int wid = tid >> 5, lane = tid & 31;
    const int gw = blockIdx.x * 32 + wid;
    const bool b0 = (blockIdx.x == 0);

    const size_t DD = (size_t)Dm * Dm * sizeof(float);
    const size_t HD = (size_t)Hm * Dm * sizeof(float);

    // ---- warm L2 with layer-0 phase-1 weights ----
    pf_l2(kw, DD); pf_l2(vw, DD); pf_l2(rw, DD);

    // ---- embed + ln0 ----
    float x = ln1024(emb[(size_t)(*tok) * Dm + tid], ln0w, ln0b, s_red);

    for (int l = 0; l < Lm; l++) {
        const float* s = state + (size_t)l * 5 * Dm;
        float* nsl = ns + (size_t)l * 5 * Dm;
        const size_t dd = (size_t)l * Dm * Dm;
        const size_t hd = (size_t)l * Hm * Dm;

        // ======== phase 1: LN1 + token-mix; k/v/r half-row dots, ALL blocks active ========
        {
            float xx = ln1024(x, ln1w + l * Dm, ln1b + l * Dm, s_red);
            float ss = s[Dm + tid];
            float mk = tmk[l * Dm + tid], mv = tmv[l * Dm + tid], mr = tmr[l * Dm + tid];
            s_v0[tid] = xx * mk + ss * (1.0f - mk);
            s_v1[tid] = xx * mv + ss * (1.0f - mv);
            s_v2[tid] = xx * mr + ss * (1.0f - mr);
            if (b0) nsl[Dm + tid] = xx;
        }
        __syncthreads();
        {
            // task t in [0,6144): mat=t>>11, row=(t&2047)>>1, half=t&1  (half-row dot4)
            int t0 = gw;
            int t1 = gw + NWG;
            bool has1 = (t1 < 6144);
            int mat0 = t0 >> 11, rem0 = t0 & 2047, row0 = rem0 >> 1, h0 = rem0 & 1;
            const float* W0 = (mat0 == 0) ? (kw + dd) : (mat0 == 1) ? (vw + dd) : (rw + dd);
            const float4* wp0 = (const float4*)(W0 + (size_t)row0 * Dm + h0 * 512);
            const float* xs0 = ((mat0 == 0) ? s_v0 : (mat0 == 1) ? s_v1 : s_v2) + h0 * 512;
            int mat1 = t1 >> 11, rem1 = t1 & 2047, row1 = rem1 >> 1, h1 = rem1 & 1;
            const float* W1 = (mat1 == 0) ? (kw + dd) : (mat1 == 1) ? (vw + dd) : (rw + dd);
            const float4* wp1 = (const float4*)(W1 + (size_t)row1 * Dm + h1 * 512);
            const float* xs1 = ((mat1 == 0) ? s_v0 : (mat1 == 1) ? s_v1 : s_v2) + h1 * 512;

            float4 a0[4], a1[4];
#pragma unroll
            for (int j = 0; j < 4; j++) a0[j] = __ldcs(wp0 + j * 32 + lane);
            if (has1) {
#pragma unroll
                for (int j = 0; j < 4; j++) a1[j] = __ldcs(wp1 + j * 32 + lane);
            }
            const float4* x40 = (const float4*)xs0;
            float acc0 = 0.f;
#pragma unroll
            for (int j = 0; j < 4; j++) acc0 = fma4(a0[j], x40[j * 32 + lane], acc0);
            acc0 = warp_sum(acc0);
            if (lane == 0) __stcg(&g_p1[t0], acc0);
            if (has1) {
                const float4* x41 = (const float4*)xs1;
                float acc1 = 0.f;
#pragma unroll
                for (int j = 0; j < 4; j++) acc1 = fma4(a1[j], x41[j * 32 + lane], acc1);
                acc1 = warp_sum(acc1);
                if (lane == 0) __stcg(&g_p1[t1], acc1);
            }
        }
        pf_l2(ow + dd, DD);
        gsync();

        // ======== phase 2: WKV (combine partials) + ow quarter-row dots ========
        {
            float k = __ldcg(&g_p1[2 * tid])        + __ldcg(&g_p1[2 * tid + 1]);
            float v = __ldcg(&g_p1[2048 + 2 * tid]) + __ldcg(&g_p1[2048 + 2 * tid + 1]);
            float rp = __ldcg(&g_p1[4096 + 2 * tid]) + __ldcg(&g_p1[4096 + 2 * tid + 1]);
            float r = 1.0f / (1.0f + expf(-rp));
            float aa = s[2 * Dm + tid], bb = s[3 * Dm + tid], pp = s[4 * Dm + tid];
            float ww = tf[l * Dm + tid] + k;
            float p = fmaxf(pp, ww);
            float e1 = expf(pp - p), e2 = expf(ww - p);
            float wkv = (e1 * aa + e2 * v) / (e1 * bb + e2);
            float ww2 = pp + td[l * Dm + tid];
            float p2 = fmaxf(ww2, k);
            float f1 = expf(ww2 - p2), f2 = expf(k - p2);
            s_v0[tid] = r * wkv;
            if (b0) {
                nsl[2 * Dm + tid] = f1 * aa + f2 * v;
                nsl[3 * Dm + tid] = f1 * bb + f2;
                nsl[4 * Dm + tid] = p2;
            }
        }
        __syncthreads();
        for (int t = gw; t < 4 * Dm; t += NWG) {
            int row = t >> 2, ch = t & 3;
            float acc = dot2((const float4*)(ow + dd + (size_t)row * Dm + ch * 256),
                             s_v0 + ch * 256, lane);
            if (lane == 0) __stcg(&g_po[ch * Dm + row], acc);
        }
        pf_l2(fkw + hd, HD); pf_l2(frw + dd, DD);
        gsync();

        // ======== phase 3: residual + LN2 + FFN mix; fk/fr dots ========
        x = x + __ldcg(&g_po[tid]) + __ldcg(&g_po[Dm + tid])
              + __ldcg(&g_po[2 * Dm + tid]) + __ldcg(&g_po[3 * Dm + tid]);
        {
            float yy = ln1024(x, ln2w + l * Dm, ln2b + l * Dm, s_red);
            float sf = s[tid];
            float mk = fmk[l * Dm + tid], mr = fmr[l * Dm + tid];
            s_v0[tid] = yy * mk + sf * (1.0f - mk);
            s_v1[tid] = yy * mr + sf * (1.0f - mr);
            if (b0) nsl[tid] = yy;
        }
        __syncthreads();
        for (int t = gw; t < Hm + Dm; t += NWG) {
            bool isk = (t < Hm);
            const float* W = isk ? (fkw + hd + (size_t)t * Dm)
                                 : (frw + dd + (size_t)(t - Hm) * Dm);
            float acc = dot8((const float4*)W, isk ? s_v0 : s_v1, lane);
            if (lane == 0) {
                if (isk) { float u = fmaxf(acc, 0.0f); __stcg(&g_fk[t], u * u); }
                else     { __stcg(&g_fr[t - Hm], 1.0f / (1.0f + expf(-acc))); }
            }
        }
        pf_l2(fvw + hd, HD);
        gsync();

        // ======== phase 4: fv quarter-row dots ========
        for (int j = tid; j < Hm; j += NT) s_fk[j] = __ldcg(&g_fk[j]);
        __syncthreads();
        for (int t = gw; t < 4 * Dm; t += NWG) {
            int row = t >> 2, ch = t & 3;
            float acc = dot8((const float4*)(fvw + hd + (size_t)row * Hm + ch * Dm),
                             s_fk + ch * Dm, lane);
            if (lane == 0) __stcg(&g_pf[ch * Dm + row], acc);
        }
        if (l + 1 < Lm) {
            const size_t dd2 = (size_t)(l + 1) * Dm * Dm;
            pf_l2(kw + dd2, DD); pf_l2(vw + dd2, DD); pf_l2(rw + dd2, DD);
        }
        if (l >= Lm - 6) {   // drip-prefetch head across last 6 layers (90MB total)
            const size_t CH = (size_t)15 * 1024 * 1024;
            pf_l2((const char*)headw + (size_t)(l - (Lm - 6)) * CH, CH);
        }
        gsync();

        // ---- residual update for next layer ----
        x = x + __ldcg(&g_fr[tid]) * (__ldcg(&g_pf[tid]) + __ldcg(&g_pf[Dm + tid])
              + __ldcg(&g_pf[2 * Dm + tid]) + __ldcg(&g_pf[3 * Dm + tid]));
    }

    // ---- final LN + head matvec (2 rows/warp in flight) ----
    {
        float xf = ln1024(x, lnoutw, lnoutb, s_red);
        s_v0[tid] = xf;
    }
    __syncthreads();
    for (int t = gw; t < Vm; t += 2 * NWG) {
        int t2 = t + NWG;
        const float4* w0 = (const float4*)(headw + (size_t)t * Dm);
        const float4* x4 = (const float4*)s_v0;
        float a0 = 0.f, a1 = 0.f;
        if (t2 < Vm) {
            const float4* w1 = (const float4*)(headw + (size_t)t2 * Dm);
#pragma unroll
            for (int j = 0; j < 8; j++) {
                float4 p = __ldcs(w0 + j * 32 + lane);
                float4 q = __ldcs(w1 + j * 32 + lane);
                float4 c = x4[j * 32 + lane];
                a0 = fma4(p, c, a0);
                a1 = fma4(q, c, a1);
            }
            a0 = warp_sum(a0); a1 = warp_sum(a1);
            if (lane == 0) { logits[t] = a0; logits[t2] = a1; }
        } else {
#pragma unroll
            for (int j = 0; j < 8; j++) a0 = fma4(__ldcs(w0 + j * 32 + lane), x4[j * 32 + lane], a0);
            a0 = warp_sum(a0);
            if (lane == 0) logits[t] = a0;
        }
    }
}

// ---------------- launch ----------------
extern "C" void kernel_launch(void* const* d_in, const int* in_sizes, int n_in,
                              void* d_out, int out_size) {
    const int*   tok    = (const int*)  d_in[0];
    const float* state  = (const float*)d_in[1];
    const float* emb    = (const float*)d_in[2];
    const float* ln0w   = (const float*)d_in[3];
    const float* ln0b   = (const float*)d_in[4];
    const float* ln1w   = (const float*)d_in[5];
    const float* ln1b   = (const float*)d_in[6];
    const float* tmk    = (const float*)d_in[7];
    const float* tmv    = (const float*)d_in[8];
    const float* tmr    = (const float*)d_in[9];
    const float* tf     = (const float*)d_in[10];
    const float* td     = (const float*)d_in[11];
    const float* kw     = (const float*)d_in[12];
    const float* vw     = (const float*)d_in[13];
    const float* rw     = (const float*)d_in[14];
    const float* ow     = (const float*)d_in[15];
    const float* ln2w   = (const float*)d_in[16];
    const float* ln2b   = (const float*)d_in[17];
    const float* fmk    = (const float*)d_in[18];
    const float* fmr    = (const float*)d_in[19];
    const float* fkw    = (const float*)d_in[20];
    const float* fvw    = (const float*)d_in[21];
    const float* frw    = (const float*)d_in[22];
    const float* lnoutw = (const float*)d_in[23];
    const float* lnoutb = (const float*)d_in[24];
    const float* headw  = (const float*)d_in[25];

    float* logits = (float*)d_out;
    float* ns     = (float*)d_out + Vm;

    rwkv_all<<<NB, NT>>>(tok, state, emb, ln0w, ln0b, ln1w, ln1b,
                         tmk, tmv, tmr, tf, td, kw, vw, rw, ow,
                         ln2w, ln2b, fmk, fmr, fkw, fvw, frw,
                         lnoutw, lnoutb, headw, logits, ns);
}